// round 3
// baseline (speedup 1.0000x reference)
#include <cuda_runtime.h>
#include <cstdint>

// Problem constants (fixed by the reference): B=8, H=16, S=1024, D=64
#define BH      128
#define SEQ     1024
#define DIM     64
#define HEADS   16
#define BQ      64          // q rows per block
#define BK      64          // k cols per tile
#define NTHREADS 128        // 16 (ty) x 8 (tx); per-thread tile 4 rows x 8 cols
#define NKT     (SEQ / BK)  // 16 k-tiles

// XOR swizzle on float4 groups: word offset within a [rows][64] fp32 tile.
// col is in words (0..63), must be a multiple of 4 for float4 access.
__device__ __forceinline__ int swz(int row, int col) {
    return row * DIM + (col ^ (((row >> 3) & 7) << 2));
}

// valid_lens dtype probe: reference declares int64 but JAX without x64 emits
// int32. First 32 bytes are valid under BOTH layouts (int32: all 8 elems;
// int64: first 4 elems). For real int64 (<1024), int32 views 1,3,5,7 are the
// guaranteed-zero high words. For int32 data they are random in [0,1024) —
// all-zero with prob ~1e-12.
__device__ __forceinline__ int load_vl(const void* vlp, int b) {
    const int* p32 = (const int*)vlp;
    bool is64 = (p32[1] == 0) && (p32[3] == 0) && (p32[5] == 0) && (p32[7] == 0);
    return is64 ? (int)((const long long*)vlp)[b] : p32[b];
}

__global__ __launch_bounds__(NTHREADS, 3)
void attn_fp32_kernel(const float* __restrict__ Qg,
                      const float* __restrict__ Kg,
                      const float* __restrict__ Vg,
                      const void* __restrict__ VL,
                      float* __restrict__ Og)
{
    extern __shared__ float smem[];
    float* Qs = smem;                    // BQ x DIM
    float* Ks = Qs + BQ * DIM;           // BK x DIM
    float* Vs = Ks + BK * DIM;           // BK x DIM
    float* Ps = Vs + BK * DIM;           // BQ x BK

    const int tid = threadIdx.x;
    const int tx  = tid & 7;             // 0..7  -> 8 cols (x8)
    const int ty  = tid >> 3;            // 0..15 -> 4 rows (x4)
    const int bh  = blockIdx.y;
    const int q0  = blockIdx.x * BQ;
    const int vl  = load_vl(VL, bh >> 4);   // batch index = bh / HEADS

    const float4* Q4 = (const float4*)(Qg + (size_t)bh * SEQ * DIM + (size_t)q0 * DIM);
    const float4* K4 = (const float4*)(Kg + (size_t)bh * SEQ * DIM);
    const float4* V4 = (const float4*)(Vg + (size_t)bh * SEQ * DIM);

    // ---- load Q tile (pre-scaled by 1/sqrt(64) = 0.125), swizzled ----
#pragma unroll
    for (int l = 0; l < (BQ * DIM / 4) / NTHREADS; ++l) {   // 8 iters
        int idx = l * NTHREADS + tid;                       // 0..1023
        int r = idx >> 4, g = idx & 15;                     // 16 float4 per row
        float4 v = Q4[idx];
        v.x *= 0.125f; v.y *= 0.125f; v.z *= 0.125f; v.w *= 0.125f;
        *(float4*)&Qs[swz(r, g * 4)] = v;
    }

    // per-thread output accumulators and softmax state (rows r = 4*ty+i)
    float o[4][8];
    float mrow[4], lrow[4];
#pragma unroll
    for (int i = 0; i < 4; ++i) {
        mrow[i] = -1e30f;
        lrow[i] = 0.0f;
#pragma unroll
        for (int j = 0; j < 8; ++j) o[i][j] = 0.0f;
    }

#pragma unroll 1
    for (int kt = 0; kt < NKT; ++kt) {
        const int k0 = kt * BK;

        // ---- load K/V tiles (swizzled) ----
#pragma unroll
        for (int l = 0; l < 8; ++l) {
            int idx = l * NTHREADS + tid;
            int r = idx >> 4, g = idx & 15;
            int off = swz(r, g * 4);
            *(float4*)&Ks[off] = K4[k0 * (DIM / 4) + idx];
            *(float4*)&Vs[off] = V4[k0 * (DIM / 4) + idx];
        }
        __syncthreads();

        // ---- GEMM1: s[i][j] = sum_d Qs[4ty+i][d] * Ks[8tx+j][d] ----
        float s[4][8];
#pragma unroll
        for (int i = 0; i < 4; ++i)
#pragma unroll
            for (int j = 0; j < 8; ++j) s[i][j] = 0.0f;

#pragma unroll 4
        for (int kk = 0; kk < DIM; kk += 4) {
            float4 a[4], b[8];
#pragma unroll
            for (int i = 0; i < 4; ++i)
                a[i] = *(const float4*)&Qs[swz(4 * ty + i, kk)];
#pragma unroll
            for (int j = 0; j < 8; ++j)
                b[j] = *(const float4*)&Ks[swz(8 * tx + j, kk)];
#pragma unroll
            for (int i = 0; i < 4; ++i) {
#pragma unroll
                for (int j = 0; j < 8; ++j) {
                    s[i][j] += a[i].x * b[j].x;
                    s[i][j] += a[i].y * b[j].y;
                    s[i][j] += a[i].z * b[j].z;
                    s[i][j] += a[i].w * b[j].w;
                }
            }
        }

        // ---- mask (fill 1e-6, NOT -inf) + online softmax update ----
#pragma unroll
        for (int i = 0; i < 4; ++i) {
#pragma unroll
            for (int j = 0; j < 8; ++j) {
                int c = k0 + 8 * tx + j;
                if (c >= vl) s[i][j] = 1e-6f;
            }
            float tm = s[i][0];
#pragma unroll
            for (int j = 1; j < 8; ++j) tm = fmaxf(tm, s[i][j]);
            // row spans 8 consecutive lanes (same ty)
            tm = fmaxf(tm, __shfl_xor_sync(0xffffffffu, tm, 1));
            tm = fmaxf(tm, __shfl_xor_sync(0xffffffffu, tm, 2));
            tm = fmaxf(tm, __shfl_xor_sync(0xffffffffu, tm, 4));

            float mn = fmaxf(mrow[i], tm);
            float f  = __expf(mrow[i] - mn);
            float rs = 0.0f;
#pragma unroll
            for (int j = 0; j < 8; ++j) {
                s[i][j] = __expf(s[i][j] - mn);
                rs += s[i][j];
            }
            rs += __shfl_xor_sync(0xffffffffu, rs, 1);
            rs += __shfl_xor_sync(0xffffffffu, rs, 2);
            rs += __shfl_xor_sync(0xffffffffu, rs, 4);

            lrow[i] = lrow[i] * f + rs;
            mrow[i] = mn;
#pragma unroll
            for (int j = 0; j < 8; ++j) o[i][j] *= f;

            // write P row to smem (swizzled, 2x STS.128)
            *(float4*)&Ps[swz(4 * ty + i, 8 * tx)]     = make_float4(s[i][0], s[i][1], s[i][2], s[i][3]);
            *(float4*)&Ps[swz(4 * ty + i, 8 * tx + 4)] = make_float4(s[i][4], s[i][5], s[i][6], s[i][7]);
        }
        __syncthreads();

        // ---- GEMM2: o[i][j] += sum_c Ps[4ty+i][c] * Vs[c][8tx+j] ----
#pragma unroll 4
        for (int c4 = 0; c4 < BK; c4 += 4) {
            float pr[4][4];
#pragma unroll
            for (int i = 0; i < 4; ++i) {
                float4 p = *(const float4*)&Ps[swz(4 * ty + i, c4)];
                pr[i][0] = p.x; pr[i][1] = p.y; pr[i][2] = p.z; pr[i][3] = p.w;
            }
#pragma unroll
            for (int cc = 0; cc < 4; ++cc) {
                float4 v0 = *(const float4*)&Vs[swz(c4 + cc, 8 * tx)];
                float4 v1 = *(const float4*)&Vs[swz(c4 + cc, 8 * tx + 4)];
                float vv[8] = {v0.x, v0.y, v0.z, v0.w, v1.x, v1.y, v1.z, v1.w};
#pragma unroll
                for (int i = 0; i < 4; ++i) {
#pragma unroll
                    for (int j = 0; j < 8; ++j)
                        o[i][j] += pr[i][cc] * vv[j];
                }
            }
        }
        __syncthreads();
    }

    // ---- finalize: divide by l, write out ----
#pragma unroll
    for (int i = 0; i < 4; ++i) {
        float inv = 1.0f / lrow[i];
        int r = q0 + 4 * ty + i;
        float4 w0 = make_float4(o[i][0] * inv, o[i][1] * inv, o[i][2] * inv, o[i][3] * inv);
        float4 w1 = make_float4(o[i][4] * inv, o[i][5] * inv, o[i][6] * inv, o[i][7] * inv);
        float* outp = Og + (size_t)bh * SEQ * DIM + (size_t)r * DIM + 8 * tx;
        *(float4*)(outp)     = w0;
        *(float4*)(outp + 4) = w1;
    }
}

extern "C" void kernel_launch(void* const* d_in, const int* in_sizes, int n_in,
                              void* d_out, int out_size) {
    const float* Q  = (const float*)d_in[0];
    const float* K  = (const float*)d_in[1];
    const float* V  = (const float*)d_in[2];
    const void*  VL = (const void*)d_in[3];
    float*       O  = (float*)d_out;

    const int smem_bytes = 4 * BQ * DIM * (int)sizeof(float);  // 64 KB
    cudaFuncSetAttribute(attn_fp32_kernel,
                         cudaFuncAttributeMaxDynamicSharedMemorySize, smem_bytes);

    dim3 grid(SEQ / BQ, BH);   // (16, 128)
    attn_fp32_kernel<<<grid, NTHREADS, smem_bytes>>>(Q, K, V, VL, O);
}

// round 6
// speedup vs baseline: 3.5959x; 3.5959x over previous
#include <cuda_runtime.h>
#include <cuda_bf16.h>
#include <cstdint>

// Problem constants: B=8, H=16, S=1024, D=64
#define SEQ  1024
#define DIM  64
#define BQ   128          // q rows per CTA
#define BK   64           // keys per tile
#define NKT  16
#define NTH  256          // 8 warps; warp w owns rows 16w..16w+15

// smem byte offsets (tiles are [rows][64] bf16, 128B rows, XOR-swizzled)
#define SM_QHI 0
#define SM_QLO 16384
#define SM_KHI 32768
#define SM_KLO 40960
#define SM_VHI 49152
#define SM_VLO 57344
#define SMEM_SZ 65536

__device__ __forceinline__ uint32_t smem_u32(const void* p) {
    uint32_t a;
    asm("{ .reg .u64 t; cvta.to.shared.u64 t, %1; cvt.u32.u64 %0, t; }" : "=r"(a) : "l"(p));
    return a;
}
__device__ __forceinline__ void ldsm4(uint32_t* f, uint32_t a) {
    asm volatile("ldmatrix.sync.aligned.m8n8.x4.shared.b16 {%0,%1,%2,%3}, [%4];"
                 : "=r"(f[0]), "=r"(f[1]), "=r"(f[2]), "=r"(f[3]) : "r"(a));
}
__device__ __forceinline__ void ldsm4t(uint32_t* f, uint32_t a) {
    asm volatile("ldmatrix.sync.aligned.m8n8.x4.trans.shared.b16 {%0,%1,%2,%3}, [%4];"
                 : "=r"(f[0]), "=r"(f[1]), "=r"(f[2]), "=r"(f[3]) : "r"(a));
}
__device__ __forceinline__ void mma16816(float* c, const uint32_t* a, const uint32_t* b) {
    asm volatile("mma.sync.aligned.m16n8k16.row.col.f32.bf16.bf16.f32 "
                 "{%0,%1,%2,%3},{%4,%5,%6,%7},{%8,%9},{%0,%1,%2,%3};"
                 : "+f"(c[0]), "+f"(c[1]), "+f"(c[2]), "+f"(c[3])
                 : "r"(a[0]), "r"(a[1]), "r"(a[2]), "r"(a[3]), "r"(b[0]), "r"(b[1]));
}
// split float pair into packed bf16x2 hi/lo (low 16 bits = first elem)
__device__ __forceinline__ void split2(float a, float b, uint32_t& whi, uint32_t& wlo) {
    __nv_bfloat162 h = __floats2bfloat162_rn(a, b);
    float ra = a - __bfloat162float(h.x);
    float rb = b - __bfloat162float(h.y);
    __nv_bfloat162 lo = __floats2bfloat162_rn(ra, rb);
    whi = *(uint32_t*)&h;
    wlo = *(uint32_t*)&lo;
}
// valid_lens dtype probe (reference says int64; JAX w/o x64 emits int32)
__device__ __forceinline__ int load_vl(const void* vlp, int b) {
    const int* p32 = (const int*)vlp;
    bool is64 = (p32[1] == 0) && (p32[3] == 0) && (p32[5] == 0) && (p32[7] == 0);
    return is64 ? (int)((const long long*)vlp)[b] : p32[b];
}

__global__ __launch_bounds__(NTH, 1)
void attn_hmma_kernel(const float* __restrict__ Qg,
                      const float* __restrict__ Kg,
                      const float* __restrict__ Vg,
                      const void* __restrict__ VL,
                      float* __restrict__ Og)
{
    extern __shared__ __align__(1024) char smem[];
    const uint32_t sb = smem_u32(smem);
    const int tid = threadIdx.x;
    const int w   = tid >> 5;
    const int l   = tid & 31;
    const int bh  = blockIdx.y;
    const int q0  = blockIdx.x * BQ;
    const int vl  = load_vl(VL, bh >> 4);

    const float4* Q4 = (const float4*)(Qg + (size_t)bh * SEQ * DIM + (size_t)q0 * DIM);
    const float4* K4 = (const float4*)(Kg + (size_t)bh * SEQ * DIM);
    const float4* V4 = (const float4*)(Vg + (size_t)bh * SEQ * DIM);

    // ---- Q: load, scale 0.125, split hi/lo -> smem (once) ----
#pragma unroll
    for (int i = 0; i < 8; ++i) {                 // 2048 float4 / 256 thr
        int idx = i * NTH + tid;
        int row = idx >> 4, grp = idx & 15;
        float4 x = Q4[idx];
        x.x *= 0.125f; x.y *= 0.125f; x.z *= 0.125f; x.w *= 0.125f;
        uint32_t h0, l0, h1, l1;
        split2(x.x, x.y, h0, l0);
        split2(x.z, x.w, h1, l1);
        uint32_t off = row * 128 + ((grp * 8) ^ ((row & 7) << 4));
        *(uint2*)(smem + SM_QHI + off) = make_uint2(h0, h1);
        *(uint2*)(smem + SM_QLO + off) = make_uint2(l0, l1);
    }

    // prefetch K/V tile 0 into registers
    float4 kp[4], vp[4];
#pragma unroll
    for (int i = 0; i < 4; ++i) { kp[i] = K4[i * NTH + tid]; vp[i] = V4[i * NTH + tid]; }

    float O[8][4];
#pragma unroll
    for (int j = 0; j < 8; ++j)
#pragma unroll
        for (int e = 0; e < 4; ++e) O[j][e] = 0.0f;
    float lsA = 0.0f, lsB = 0.0f;

    // per-lane ldmatrix addressing constants
    const int arow = (w << 4) + ((l >> 3) & 1) * 8 + (l & 7);  // Q A-frag row
    const uint32_t aX   = (uint32_t)((arow & 7) << 4);
    const uint32_t aRB  = (uint32_t)(arow * 128);
    const uint32_t aKE  = (uint32_t)((l >> 4) << 4);           // +16B for k8..15 groups
    const uint32_t lx   = (uint32_t)((l & 7) << 4);            // swizzle xor for K/V rows

#pragma unroll 1
    for (int kt = 0; kt < NKT; ++kt) {
        const int k0 = kt * BK;

        // ---- store prefetched K/V tile: split -> smem ----
#pragma unroll
        for (int i = 0; i < 4; ++i) {
            int idx = i * NTH + tid;
            int row = idx >> 4, grp = idx & 15;
            uint32_t off = row * 128 + ((grp * 8) ^ ((row & 7) << 4));
            uint32_t h0, l0, h1, l1;
            split2(kp[i].x, kp[i].y, h0, l0);
            split2(kp[i].z, kp[i].w, h1, l1);
            *(uint2*)(smem + SM_KHI + off) = make_uint2(h0, h1);
            *(uint2*)(smem + SM_KLO + off) = make_uint2(l0, l1);
            split2(vp[i].x, vp[i].y, h0, l0);
            split2(vp[i].z, vp[i].w, h1, l1);
            *(uint2*)(smem + SM_VHI + off) = make_uint2(h0, h1);
            *(uint2*)(smem + SM_VLO + off) = make_uint2(l0, l1);
        }
        __syncthreads();

        // prefetch next tile (clamped; in flight during MMAs)
        {
            int nkt = (kt < NKT - 1) ? kt + 1 : NKT - 1;
#pragma unroll
            for (int i = 0; i < 4; ++i) {
                kp[i] = K4[nkt * 1024 + i * NTH + tid];
                vp[i] = V4[nkt * 1024 + i * NTH + tid];
            }
        }

        // ---- load Q A-fragments (hi/lo), 4 k-frags each ----
        uint32_t qh[4][4], ql[4][4];
#pragma unroll
        for (int kf = 0; kf < 4; ++kf) {
            uint32_t ao = aRB + (((uint32_t)(kf * 32) + aKE) ^ aX);
            ldsm4(qh[kf], sb + SM_QHI + ao);
            ldsm4(ql[kf], sb + SM_QLO + ao);
        }

        // ---- GEMM1: S = (qh+ql)(kh+kl)^T, 3-term split ----
        float S[8][4];
#pragma unroll
        for (int j = 0; j < 8; ++j) {
#pragma unroll
            for (int e = 0; e < 4; ++e) S[j][e] = 0.0f;
            uint32_t bkh[4][2], bkl[4][2];
            uint32_t rb = (uint32_t)((8 * j + (l & 7)) * 128);
#pragma unroll
            for (int c = 0; c < 4; c += 2) {
                uint32_t ko = ((uint32_t)(c * 32) + ((uint32_t)(l >> 3) << 4)) ^ lx;
                ldsm4(&bkh[c][0], sb + SM_KHI + rb + ko);
                ldsm4(&bkl[c][0], sb + SM_KLO + rb + ko);
            }
#pragma unroll
            for (int kf = 0; kf < 4; ++kf) {
                mma16816(S[j], qh[kf], bkh[kf]);
                mma16816(S[j], qh[kf], bkl[kf]);
                mma16816(S[j], ql[kf], bkh[kf]);
            }
        }

        // ---- mask (1e-6 fill) + exp + lsum + pack P into A-frag layout ----
        uint32_t ph[4][4], pl[4][4];
#pragma unroll
        for (int j = 0; j < 8; ++j) {
            int cA = k0 + 8 * j + 2 * (l & 3);
            float c0 = (cA     < vl) ? S[j][0] : 1e-6f;
            float c1 = (cA + 1 < vl) ? S[j][1] : 1e-6f;
            float c2 = (cA     < vl) ? S[j][2] : 1e-6f;
            float c3 = (cA + 1 < vl) ? S[j][3] : 1e-6f;
            float p0 = __expf(c0), p1 = __expf(c1);
            float p2 = __expf(c2), p3 = __expf(c3);
            lsA += p0 + p1;
            lsB += p2 + p3;
            int kf = j >> 1, h = (j & 1) * 2;
            split2(p0, p1, ph[kf][h],     pl[kf][h]);
            split2(p2, p3, ph[kf][h + 1], pl[kf][h + 1]);
        }

        // ---- GEMM2: O += (ph+pl)(vh+vl), 3-term split ----
#pragma unroll
        for (int j = 0; j < 8; ++j) {
            uint32_t bvh[4][2], bvl[4][2];
#pragma unroll
            for (int c = 0; c < 4; c += 2) {
                int vrow = (c << 4) + ((l >> 4) << 4) + (((l >> 3) & 1) << 3) + (l & 7);
                uint32_t vo = (uint32_t)(vrow * 128) + (((uint32_t)(16 * j)) ^ lx);
                ldsm4t(&bvh[c][0], sb + SM_VHI + vo);
                ldsm4t(&bvl[c][0], sb + SM_VLO + vo);
            }
#pragma unroll
            for (int kf = 0; kf < 4; ++kf) {
                mma16816(O[j], ph[kf], bvh[kf]);
                mma16816(O[j], ph[kf], bvl[kf]);
                mma16816(O[j], pl[kf], bvh[kf]);
            }
        }
        __syncthreads();
    }

    // ---- epilogue: reduce lsum over the 4 lanes of each row, write out ----
    lsA += __shfl_xor_sync(0xffffffffu, lsA, 1);
    lsA += __shfl_xor_sync(0xffffffffu, lsA, 2);
    lsB += __shfl_xor_sync(0xffffffffu, lsB, 1);
    lsB += __shfl_xor_sync(0xffffffffu, lsB, 2);
    float invA = 1.0f / lsA, invB = 1.0f / lsB;

    int r0 = q0 + (w << 4) + (l >> 2);
    int r1 = r0 + 8;
    float* o0 = Og + (size_t)bh * SEQ * DIM + (size_t)r0 * DIM + 2 * (l & 3);
    float* o1 = Og + (size_t)bh * SEQ * DIM + (size_t)r1 * DIM + 2 * (l & 3);
#pragma unroll
    for (int j = 0; j < 8; ++j) {
        *(float2*)(o0 + 8 * j) = make_float2(O[j][0] * invA, O[j][1] * invA);
        *(float2*)(o1 + 8 * j) = make_float2(O[j][2] * invB, O[j][3] * invB);
    }
}

extern "C" void kernel_launch(void* const* d_in, const int* in_sizes, int n_in,
                              void* d_out, int out_size) {
    const float* Q  = (const float*)d_in[0];
    const float* K  = (const float*)d_in[1];
    const float* V  = (const float*)d_in[2];
    const void*  VL = (const void*)d_in[3];
    float*       O  = (float*)d_out;

    cudaFuncSetAttribute(attn_hmma_kernel,
                         cudaFuncAttributeMaxDynamicSharedMemorySize, SMEM_SZ);

    dim3 grid(SEQ / BQ, 128);   // (8, 128) = 1024 CTAs
    attn_hmma_kernel<<<grid, NTH, SMEM_SZ>>>(Q, K, V, VL, O);
}

// round 12
// speedup vs baseline: 6.5201x; 1.8132x over previous
#include <cuda_runtime.h>
#include <cuda_bf16.h>
#include <cstdint>

// Problem constants: B=8, H=16, S=1024, D=64
#define SEQ  1024
#define DIM  64
#define BQ   128          // q rows per CTA
#define BK   64           // keys per tile
#define NKT  16
#define NTH  256          // 8 warps; warp w owns rows 16w..16w+15

// smem byte offsets (tiles are [rows][64] bf16, 128B rows, XOR-swizzled)
#define SM_QHI 0
#define SM_QLO 16384
#define SM_KHI 32768
#define SM_KLO 40960
#define SM_VHI 49152
#define SM_VLO 57344
#define SMEM_SZ 65536

// per-(bh) ALIGNED tail column sums: T[bh][d] = sum_{k >= 64*ceil(vl/64)} V[bh][k][d]
// (keys in [vl, 64*ceil(vl/64)) are handled IN-LOOP via the 1e-6 masked fill;
//  summing from vl here double-counts them — that was the round-7 bug)
__device__ float g_T[128 * DIM];

__device__ __forceinline__ uint32_t smem_u32(const void* p) {
    uint32_t a;
    asm("{ .reg .u64 t; cvta.to.shared.u64 t, %1; cvt.u32.u64 %0, t; }" : "=r"(a) : "l"(p));
    return a;
}
__device__ __forceinline__ void ldsm4(uint32_t* f, uint32_t a) {
    asm volatile("ldmatrix.sync.aligned.m8n8.x4.shared.b16 {%0,%1,%2,%3}, [%4];"
                 : "=r"(f[0]), "=r"(f[1]), "=r"(f[2]), "=r"(f[3]) : "r"(a));
}
__device__ __forceinline__ void ldsm4t(uint32_t* f, uint32_t a) {
    asm volatile("ldmatrix.sync.aligned.m8n8.x4.trans.shared.b16 {%0,%1,%2,%3}, [%4];"
                 : "=r"(f[0]), "=r"(f[1]), "=r"(f[2]), "=r"(f[3]) : "r"(a));
}
__device__ __forceinline__ void mma16816(float* c, const uint32_t* a, const uint32_t* b) {
    asm volatile("mma.sync.aligned.m16n8k16.row.col.f32.bf16.bf16.f32 "
                 "{%0,%1,%2,%3},{%4,%5,%6,%7},{%8,%9},{%0,%1,%2,%3};"
                 : "+f"(c[0]), "+f"(c[1]), "+f"(c[2]), "+f"(c[3])
                 : "r"(a[0]), "r"(a[1]), "r"(a[2]), "r"(a[3]), "r"(b[0]), "r"(b[1]));
}
// split float pair into packed bf16x2 hi/lo (low 16 bits = first elem)
__device__ __forceinline__ void split2(float a, float b, uint32_t& whi, uint32_t& wlo) {
    __nv_bfloat162 h = __floats2bfloat162_rn(a, b);
    float ra = a - __bfloat162float(h.x);
    float rb = b - __bfloat162float(h.y);
    __nv_bfloat162 lo = __floats2bfloat162_rn(ra, rb);
    whi = *(uint32_t*)&h;
    wlo = *(uint32_t*)&lo;
}
// valid_lens dtype probe (reference says int64; JAX w/o x64 emits int32)
__device__ __forceinline__ int load_vl(const void* vlp, int b) {
    const int* p32 = (const int*)vlp;
    bool is64 = (p32[1] == 0) && (p32[3] == 0) && (p32[5] == 0) && (p32[7] == 0);
    return is64 ? (int)((const long long*)vlp)[b] : p32[b];
}

// ---- prepass: ALIGNED tail column sums over keys beyond the last processed tile ----
__global__ void tail_colsum_kernel(const float* __restrict__ Vg,
                                   const void* __restrict__ VL)
{
    __shared__ float red[256];
    const int bh = blockIdx.x;              // 128 blocks
    const int vl = load_vl(VL, bh >> 4);
    const int start = ((vl + BK - 1) >> 6) << 6;   // 64*ceil(vl/64)
    const int t  = threadIdx.x;             // 256 threads
    const int d  = t & 63, rg = t >> 6;     // 4 row-groups x 64 dims
    const float* Vb = Vg + (size_t)bh * SEQ * DIM;
    float acc = 0.0f;
    for (int r = start + rg; r < SEQ; r += 4) acc += Vb[r * DIM + d];
    red[t] = acc;
    __syncthreads();
    if (rg == 0)
        g_T[bh * DIM + d] = red[d] + red[64 + d] + red[128 + d] + red[192 + d];
}

__global__ __launch_bounds__(NTH, 1)
void attn_hmma_kernel(const float* __restrict__ Qg,
                      const float* __restrict__ Kg,
                      const float* __restrict__ Vg,
                      const void* __restrict__ VL,
                      float* __restrict__ Og)
{
    extern __shared__ __align__(1024) char smem[];
    const uint32_t sb = smem_u32(smem);
    const int tid = threadIdx.x;
    const int w   = tid >> 5;
    const int l   = tid & 31;
    const int bh  = blockIdx.y;
    const int q0  = blockIdx.x * BQ;
    const int vl  = load_vl(VL, bh >> 4);
    const int nt  = (vl + BK - 1) >> 6;      // tiles with any valid key

    const float4* Q4 = (const float4*)(Qg + (size_t)bh * SEQ * DIM + (size_t)q0 * DIM);
    const float4* K4 = (const float4*)(Kg + (size_t)bh * SEQ * DIM);
    const float4* V4 = (const float4*)(Vg + (size_t)bh * SEQ * DIM);

    // ---- Q: load, scale 0.125, split hi/lo -> smem (once) ----
#pragma unroll
    for (int i = 0; i < 8; ++i) {                 // 2048 float4 / 256 thr
        int idx = i * NTH + tid;
        int row = idx >> 4, grp = idx & 15;
        float4 x = Q4[idx];
        x.x *= 0.125f; x.y *= 0.125f; x.z *= 0.125f; x.w *= 0.125f;
        uint32_t h0, l0, h1, l1;
        split2(x.x, x.y, h0, l0);
        split2(x.z, x.w, h1, l1);
        uint32_t off = row * 128 + ((grp * 8) ^ ((row & 7) << 4));
        *(uint2*)(smem + SM_QHI + off) = make_uint2(h0, h1);
        *(uint2*)(smem + SM_QLO + off) = make_uint2(l0, l1);
    }

    // prefetch K/V tile 0 into registers
    float4 kp[4], vp[4];
#pragma unroll
    for (int i = 0; i < 4; ++i) { kp[i] = K4[i * NTH + tid]; vp[i] = V4[i * NTH + tid]; }

    float O[8][4];
#pragma unroll
    for (int j = 0; j < 8; ++j)
#pragma unroll
        for (int e = 0; e < 4; ++e) O[j][e] = 0.0f;
    float lsA = 0.0f, lsB = 0.0f;

    // per-lane ldmatrix addressing constants
    const int arow = (w << 4) + ((l >> 3) & 1) * 8 + (l & 7);  // Q A-frag row
    const uint32_t aX   = (uint32_t)((arow & 7) << 4);
    const uint32_t aRB  = (uint32_t)(arow * 128);
    const uint32_t aKE  = (uint32_t)((l >> 4) << 4);           // +16B for k8..15 groups
    const uint32_t lx   = (uint32_t)((l & 7) << 4);            // swizzle xor for K/V rows

    __syncthreads();   // Q smem visible

    // ---- Q A-fragments (hi/lo), hoisted: tile-invariant ----
    uint32_t qh[4][4], ql[4][4];
#pragma unroll
    for (int kf = 0; kf < 4; ++kf) {
        uint32_t ao = aRB + (((uint32_t)(kf * 32) + aKE) ^ aX);
        ldsm4(qh[kf], sb + SM_QHI + ao);
        ldsm4(ql[kf], sb + SM_QLO + ao);
    }

#pragma unroll 1
    for (int kt = 0; kt < nt; ++kt) {
        const int k0 = kt * BK;

        // ---- store prefetched K/V tile: split -> smem ----
#pragma unroll
        for (int i = 0; i < 4; ++i) {
            int idx = i * NTH + tid;
            int row = idx >> 4, grp = idx & 15;
            uint32_t off = row * 128 + ((grp * 8) ^ ((row & 7) << 4));
            uint32_t h0, l0, h1, l1;
            split2(kp[i].x, kp[i].y, h0, l0);
            split2(kp[i].z, kp[i].w, h1, l1);
            *(uint2*)(smem + SM_KHI + off) = make_uint2(h0, h1);
            *(uint2*)(smem + SM_KLO + off) = make_uint2(l0, l1);
            split2(vp[i].x, vp[i].y, h0, l0);
            split2(vp[i].z, vp[i].w, h1, l1);
            *(uint2*)(smem + SM_VHI + off) = make_uint2(h0, h1);
            *(uint2*)(smem + SM_VLO + off) = make_uint2(l0, l1);
        }
        __syncthreads();

        // prefetch next tile (clamped; in flight during MMAs)
        {
            int nkt = (kt < nt - 1) ? kt + 1 : kt;
#pragma unroll
            for (int i = 0; i < 4; ++i) {
                kp[i] = K4[nkt * 1024 + i * NTH + tid];
                vp[i] = V4[nkt * 1024 + i * NTH + tid];
            }
        }

        // ---- GEMM1: S = (qh+ql)(kh+kl)^T, 3-term split ----
        float S[8][4];
#pragma unroll
        for (int j = 0; j < 8; ++j) {
#pragma unroll
            for (int e = 0; e < 4; ++e) S[j][e] = 0.0f;
            uint32_t bkh[4][2], bkl[4][2];
            uint32_t rb = (uint32_t)((8 * j + (l & 7)) * 128);
#pragma unroll
            for (int c = 0; c < 4; c += 2) {
                uint32_t ko = ((uint32_t)(c * 32) + ((uint32_t)(l >> 3) << 4)) ^ lx;
                ldsm4(&bkh[c][0], sb + SM_KHI + rb + ko);
                ldsm4(&bkl[c][0], sb + SM_KLO + rb + ko);
            }
#pragma unroll
            for (int kf = 0; kf < 4; ++kf) {
                mma16816(S[j], qh[kf], bkh[kf]);
                mma16816(S[j], qh[kf], bkl[kf]);
                mma16816(S[j], ql[kf], bkh[kf]);
            }
        }

        // ---- mask (1e-6 fill) + exp + lsum + pack P into A-frag layout ----
        uint32_t ph[4][4], pl[4][4];
#pragma unroll
        for (int j = 0; j < 8; ++j) {
            int cA = k0 + 8 * j + 2 * (l & 3);
            float c0 = (cA     < vl) ? S[j][0] : 1e-6f;
            float c1 = (cA + 1 < vl) ? S[j][1] : 1e-6f;
            float c2 = (cA     < vl) ? S[j][2] : 1e-6f;
            float c3 = (cA + 1 < vl) ? S[j][3] : 1e-6f;
            float p0 = __expf(c0), p1 = __expf(c1);
            float p2 = __expf(c2), p3 = __expf(c3);
            lsA += p0 + p1;
            lsB += p2 + p3;
            int kf = j >> 1, h = (j & 1) * 2;
            split2(p0, p1, ph[kf][h],     pl[kf][h]);
            split2(p2, p3, ph[kf][h + 1], pl[kf][h + 1]);
        }

        // ---- GEMM2: O += (ph+pl)(vh+vl), 3-term split ----
#pragma unroll
        for (int j = 0; j < 8; ++j) {
            uint32_t bvh[4][2], bvl[4][2];
#pragma unroll
            for (int c = 0; c < 4; c += 2) {
                int vrow = (c << 4) + ((l >> 4) << 4) + (((l >> 3) & 1) << 3) + (l & 7);
                uint32_t vo = (uint32_t)(vrow * 128) + (((uint32_t)(16 * j)) ^ lx);
                ldsm4t(&bvh[c][0], sb + SM_VHI + vo);
                ldsm4t(&bvl[c][0], sb + SM_VLO + vo);
            }
#pragma unroll
            for (int kf = 0; kf < 4; ++kf) {
                mma16816(O[j], ph[kf], bvh[kf]);
                mma16816(O[j], ph[kf], bvl[kf]);
                mma16816(O[j], pl[kf], bvh[kf]);
            }
        }
        __syncthreads();
    }

    // ---- epilogue ----
    // keys beyond nt*64 (never touched in-loop): each contributes p = exp(1e-6)
    const float cM    = __expf(1e-6f);
    const float tailn = (float)(SEQ - nt * BK);

    lsA += __shfl_xor_sync(0xffffffffu, lsA, 1);
    lsA += __shfl_xor_sync(0xffffffffu, lsA, 2);
    lsB += __shfl_xor_sync(0xffffffffu, lsB, 1);
    lsB += __shfl_xor_sync(0xffffffffu, lsB, 2);
    lsA += cM * tailn;
    lsB += cM * tailn;
    float invA = 1.0f / lsA, invB = 1.0f / lsB;

    // O += cM * T[bh][col]  (aligned-tail value mass, exact f32)
    const float* Tb = g_T + bh * DIM + 2 * (l & 3);
#pragma unroll
    for (int j = 0; j < 8; ++j) {
        float2 tv = *(const float2*)(Tb + 8 * j);
        O[j][0] += cM * tv.x;  O[j][1] += cM * tv.y;
        O[j][2] += cM * tv.x;  O[j][3] += cM * tv.y;
    }

    int r0 = q0 + (w << 4) + (l >> 2);
    int r1 = r0 + 8;
    float* o0 = Og + (size_t)bh * SEQ * DIM + (size_t)r0 * DIM + 2 * (l & 3);
    float* o1 = Og + (size_t)bh * SEQ * DIM + (size_t)r1 * DIM + 2 * (l & 3);
#pragma unroll
    for (int j = 0; j < 8; ++j) {
        *(float2*)(o0 + 8 * j) = make_float2(O[j][0] * invA, O[j][1] * invA);
        *(float2*)(o1 + 8 * j) = make_float2(O[j][2] * invB, O[j][3] * invB);
    }
}

extern "C" void kernel_launch(void* const* d_in, const int* in_sizes, int n_in,
                              void* d_out, int out_size) {
    const float* Q  = (const float*)d_in[0];
    const float* K  = (const float*)d_in[1];
    const float* V  = (const float*)d_in[2];
    const void*  VL = (const void*)d_in[3];
    float*       O  = (float*)d_out;

    cudaFuncSetAttribute(attn_hmma_kernel,
                         cudaFuncAttributeMaxDynamicSharedMemorySize, SMEM_SZ);

    tail_colsum_kernel<<<128, 256>>>(V, VL);

    dim3 grid(SEQ / BQ, 128);   // (8, 128) = 1024 CTAs
    attn_hmma_kernel<<<grid, NTH, SMEM_SZ>>>(Q, K, V, VL, O);
}

// round 14
// speedup vs baseline: 6.6772x; 1.0241x over previous
#include <cuda_runtime.h>
#include <cuda_bf16.h>
#include <cstdint>

// Problem constants: B=8, H=16, S=1024, D=64
#define SEQ  1024
#define DIM  64
#define BQ   64           // q rows per CTA
#define BK   32           // keys per tile
#define NTH  128          // 4 warps; warp w owns rows 16w..16w+15

// smem byte offsets (tiles are [rows][64] bf16, 128B rows, XOR-swizzled)
#define SM_QHI 0          // 64 x 128B = 8192
#define SM_QLO 8192
#define SM_KHI 16384      // 32 x 128B = 4096
#define SM_KLO 20480
#define SM_VHI 24576
#define SM_VLO 28672
#define SMEM_SZ 32768

// per-(bh) ALIGNED tail column sums: T[bh][d] = sum_{k >= BK*ceil(vl/BK)} V[bh][k][d]
// (keys in [vl, BK*ceil(vl/BK)) are handled IN-LOOP via the 1e-6 masked fill)
__device__ float g_T[128 * DIM];

__device__ __forceinline__ uint32_t smem_u32(const void* p) {
    uint32_t a;
    asm("{ .reg .u64 t; cvta.to.shared.u64 t, %1; cvt.u32.u64 %0, t; }" : "=r"(a) : "l"(p));
    return a;
}
__device__ __forceinline__ void ldsm4(uint32_t* f, uint32_t a) {
    asm volatile("ldmatrix.sync.aligned.m8n8.x4.shared.b16 {%0,%1,%2,%3}, [%4];"
                 : "=r"(f[0]), "=r"(f[1]), "=r"(f[2]), "=r"(f[3]) : "r"(a));
}
__device__ __forceinline__ void ldsm4t(uint32_t* f, uint32_t a) {
    asm volatile("ldmatrix.sync.aligned.m8n8.x4.trans.shared.b16 {%0,%1,%2,%3}, [%4];"
                 : "=r"(f[0]), "=r"(f[1]), "=r"(f[2]), "=r"(f[3]) : "r"(a));
}
__device__ __forceinline__ void mma16816(float* c, const uint32_t* a, const uint32_t* b) {
    asm volatile("mma.sync.aligned.m16n8k16.row.col.f32.bf16.bf16.f32 "
                 "{%0,%1,%2,%3},{%4,%5,%6,%7},{%8,%9},{%0,%1,%2,%3};"
                 : "+f"(c[0]), "+f"(c[1]), "+f"(c[2]), "+f"(c[3])
                 : "r"(a[0]), "r"(a[1]), "r"(a[2]), "r"(a[3]), "r"(b[0]), "r"(b[1]));
}
// split float pair into packed bf16x2 hi/lo (low 16 bits = first elem)
__device__ __forceinline__ void split2(float a, float b, uint32_t& whi, uint32_t& wlo) {
    __nv_bfloat162 h = __floats2bfloat162_rn(a, b);
    float ra = a - __bfloat162float(h.x);
    float rb = b - __bfloat162float(h.y);
    __nv_bfloat162 lo = __floats2bfloat162_rn(ra, rb);
    whi = *(uint32_t*)&h;
    wlo = *(uint32_t*)&lo;
}
// valid_lens dtype probe (reference says int64; JAX w/o x64 emits int32)
__device__ __forceinline__ int load_vl(const void* vlp, int b) {
    const int* p32 = (const int*)vlp;
    bool is64 = (p32[1] == 0) && (p32[3] == 0) && (p32[5] == 0) && (p32[7] == 0);
    return is64 ? (int)((const long long*)vlp)[b] : p32[b];
}

// ---- prepass: ALIGNED tail column sums over keys beyond the last processed tile ----
__global__ void tail_colsum_kernel(const float* __restrict__ Vg,
                                   const void* __restrict__ VL)
{
    __shared__ float red[256];
    const int bh = blockIdx.x;              // 128 blocks
    const int vl = load_vl(VL, bh >> 4);
    const int start = ((vl + BK - 1) / BK) * BK;   // BK*ceil(vl/BK)
    const int t  = threadIdx.x;             // 256 threads
    const int d  = t & 63, rg = t >> 6;     // 4 row-groups x 64 dims
    const float* Vb = Vg + (size_t)bh * SEQ * DIM;
    float acc = 0.0f;
    for (int r = start + rg; r < SEQ; r += 4) acc += Vb[r * DIM + d];
    red[t] = acc;
    __syncthreads();
    if (rg == 0)
        g_T[bh * DIM + d] = red[d] + red[64 + d] + red[128 + d] + red[192 + d];
}

__global__ __launch_bounds__(NTH, 2)
void attn_hmma_kernel(const float* __restrict__ Qg,
                      const float* __restrict__ Kg,
                      const float* __restrict__ Vg,
                      const void* __restrict__ VL,
                      float* __restrict__ Og)
{
    extern __shared__ __align__(1024) char smem[];
    const uint32_t sb = smem_u32(smem);
    const int tid = threadIdx.x;
    const int w   = tid >> 5;                // 0..3
    const int l   = tid & 31;
    const int bh  = blockIdx.y;
    const int q0  = blockIdx.x * BQ;
    const int vl  = load_vl(VL, bh >> 4);
    const int nt  = (vl + BK - 1) / BK;      // 32-key tiles with any valid key

    const float4* Q4 = (const float4*)(Qg + (size_t)bh * SEQ * DIM + (size_t)q0 * DIM);
    const float4* K4 = (const float4*)(Kg + (size_t)bh * SEQ * DIM);
    const float4* V4 = (const float4*)(Vg + (size_t)bh * SEQ * DIM);

    // ---- Q: load, scale 0.125, split hi/lo -> smem (once) ----
#pragma unroll
    for (int i = 0; i < 8; ++i) {                 // 1024 float4 / 128 thr
        int idx = i * NTH + tid;
        int row = idx >> 4, grp = idx & 15;
        float4 x = Q4[idx];
        x.x *= 0.125f; x.y *= 0.125f; x.z *= 0.125f; x.w *= 0.125f;
        uint32_t h0, l0, h1, l1;
        split2(x.x, x.y, h0, l0);
        split2(x.z, x.w, h1, l1);
        uint32_t off = row * 128 + ((grp * 8) ^ ((row & 7) << 4));
        *(uint2*)(smem + SM_QHI + off) = make_uint2(h0, h1);
        *(uint2*)(smem + SM_QLO + off) = make_uint2(l0, l1);
    }

    // prefetch K/V tile 0 into registers (32x64 f32 = 512 f4 each / 128 thr = 4)
    float4 kp[4], vp[4];
#pragma unroll
    for (int i = 0; i < 4; ++i) { kp[i] = K4[i * NTH + tid]; vp[i] = V4[i * NTH + tid]; }

    float O[8][4];
#pragma unroll
    for (int j = 0; j < 8; ++j)
#pragma unroll
        for (int e = 0; e < 4; ++e) O[j][e] = 0.0f;
    float lsA = 0.0f, lsB = 0.0f;

    // per-lane ldmatrix addressing constants
    const int arow = (w << 4) + ((l >> 3) & 1) * 8 + (l & 7);  // Q A-frag row
    const uint32_t aX   = (uint32_t)((arow & 7) << 4);
    const uint32_t aRB  = (uint32_t)(arow * 128);
    const uint32_t aKE  = (uint32_t)((l >> 4) << 4);           // +16B for k8..15 groups
    const uint32_t lx   = (uint32_t)((l & 7) << 4);            // swizzle xor for K/V rows

    __syncthreads();   // Q smem visible

    // ---- Q A-fragments (hi/lo), hoisted: tile-invariant ----
    uint32_t qh[4][4], ql[4][4];
#pragma unroll
    for (int kf = 0; kf < 4; ++kf) {
        uint32_t ao = aRB + (((uint32_t)(kf * 32) + aKE) ^ aX);
        ldsm4(qh[kf], sb + SM_QHI + ao);
        ldsm4(ql[kf], sb + SM_QLO + ao);
    }

#pragma unroll 1
    for (int kt = 0; kt < nt; ++kt) {
        const int k0 = kt * BK;

        // ---- store prefetched K/V tile: split -> smem ----
#pragma unroll
        for (int i = 0; i < 4; ++i) {
            int idx = i * NTH + tid;
            int row = idx >> 4, grp = idx & 15;
            uint32_t off = row * 128 + ((grp * 8) ^ ((row & 7) << 4));
            uint32_t h0, l0, h1, l1;
            split2(kp[i].x, kp[i].y, h0, l0);
            split2(kp[i].z, kp[i].w, h1, l1);
            *(uint2*)(smem + SM_KHI + off) = make_uint2(h0, h1);
            *(uint2*)(smem + SM_KLO + off) = make_uint2(l0, l1);
            split2(vp[i].x, vp[i].y, h0, l0);
            split2(vp[i].z, vp[i].w, h1, l1);
            *(uint2*)(smem + SM_VHI + off) = make_uint2(h0, h1);
            *(uint2*)(smem + SM_VLO + off) = make_uint2(l0, l1);
        }
        __syncthreads();

        // prefetch next tile (clamped; in flight during MMAs)
        {
            int nkt = (kt < nt - 1) ? kt + 1 : kt;
#pragma unroll
            for (int i = 0; i < 4; ++i) {
                kp[i] = K4[nkt * 512 + i * NTH + tid];
                vp[i] = V4[nkt * 512 + i * NTH + tid];
            }
        }

        // ---- GEMM1: S = (qh+ql)(kh+kl)^T, 3-term split, paired accumulators ----
        float S[4][4];
#pragma unroll
        for (int jp = 0; jp < 2; ++jp) {
            const int j0 = 2 * jp, j1 = 2 * jp + 1;
#pragma unroll
            for (int e = 0; e < 4; ++e) { S[j0][e] = 0.0f; S[j1][e] = 0.0f; }
            uint32_t b0h[4][2], b0l[4][2], b1h[4][2], b1l[4][2];
            uint32_t rb0 = (uint32_t)((8 * j0 + (l & 7)) * 128);
            uint32_t rb1 = (uint32_t)((8 * j1 + (l & 7)) * 128);
#pragma unroll
            for (int c = 0; c < 4; c += 2) {
                uint32_t ko = ((uint32_t)(c * 32) + ((uint32_t)(l >> 3) << 4)) ^ lx;
                ldsm4(&b0h[c][0], sb + SM_KHI + rb0 + ko);
                ldsm4(&b0l[c][0], sb + SM_KLO + rb0 + ko);
                ldsm4(&b1h[c][0], sb + SM_KHI + rb1 + ko);
                ldsm4(&b1l[c][0], sb + SM_KLO + rb1 + ko);
            }
#pragma unroll
            for (int kf = 0; kf < 4; ++kf) {
                mma16816(S[j0], qh[kf], b0h[kf]);
                mma16816(S[j1], qh[kf], b1h[kf]);
                mma16816(S[j0], qh[kf], b0l[kf]);
                mma16816(S[j1], qh[kf], b1l[kf]);
                mma16816(S[j0], ql[kf], b0h[kf]);
                mma16816(S[j1], ql[kf], b1h[kf]);
            }
        }

        // ---- mask (1e-6 fill) + exp + lsum + pack P into A-frag layout ----
        uint32_t ph[2][4], pl[2][4];
#pragma unroll
        for (int j = 0; j < 4; ++j) {
            int cA = k0 + 8 * j + 2 * (l & 3);
            float c0 = (cA     < vl) ? S[j][0] : 1e-6f;
            float c1 = (cA + 1 < vl) ? S[j][1] : 1e-6f;
            float c2 = (cA     < vl) ? S[j][2] : 1e-6f;
            float c3 = (cA + 1 < vl) ? S[j][3] : 1e-6f;
            float p0 = __expf(c0), p1 = __expf(c1);
            float p2 = __expf(c2), p3 = __expf(c3);
            lsA += p0 + p1;
            lsB += p2 + p3;
            int kf = j >> 1, h = (j & 1) * 2;
            split2(p0, p1, ph[kf][h],     pl[kf][h]);
            split2(p2, p3, ph[kf][h + 1], pl[kf][h + 1]);
        }

        // ---- GEMM2: O += (ph+pl)(vh+vl), 3-term split, paired accumulators ----
        {
            const int vrow = ((l >> 4) << 4) + (((l >> 3) & 1) << 3) + (l & 7);
            const uint32_t vrb = (uint32_t)(vrow * 128);
#pragma unroll
            for (int jp = 0; jp < 4; ++jp) {
                const int j0 = 2 * jp, j1 = 2 * jp + 1;
                uint32_t b0h[2][2], b0l[2][2], b1h[2][2], b1l[2][2];
                uint32_t vo0 = vrb + (((uint32_t)(16 * j0)) ^ lx);
                uint32_t vo1 = vrb + (((uint32_t)(16 * j1)) ^ lx);
                ldsm4t(&b0h[0][0], sb + SM_VHI + vo0);
                ldsm4t(&b0l[0][0], sb + SM_VLO + vo0);
                ldsm4t(&b1h[0][0], sb + SM_VHI + vo1);
                ldsm4t(&b1l[0][0], sb + SM_VLO + vo1);
#pragma unroll
                for (int kf = 0; kf < 2; ++kf) {
                    mma16816(O[j0], ph[kf], b0h[kf]);
                    mma16816(O[j1], ph[kf], b1h[kf]);
                    mma16816(O[j0], ph[kf], b0l[kf]);
                    mma16816(O[j1], ph[kf], b1l[kf]);
                    mma16816(O[j0], pl[kf], b0h[kf]);
                    mma16816(O[j1], pl[kf], b1h[kf]);
                }
            }
        }
        __syncthreads();
    }

    // ---- epilogue ----
    // keys beyond nt*BK (never touched in-loop): each contributes p = exp(1e-6)
    const float cM    = __expf(1e-6f);
    const float tailn = (float)(SEQ - nt * BK);

    lsA += __shfl_xor_sync(0xffffffffu, lsA, 1);
    lsA += __shfl_xor_sync(0xffffffffu, lsA, 2);
    lsB += __shfl_xor_sync(0xffffffffu, lsB, 1);
    lsB += __shfl_xor_sync(0xffffffffu, lsB, 2);
    lsA += cM * tailn;
    lsB += cM * tailn;
    float invA = 1.0f / lsA, invB = 1.0f / lsB;

    // O += cM * T[bh][col]  (aligned-tail value mass, exact f32)
    const float* Tb = g_T + bh * DIM + 2 * (l & 3);
#pragma unroll
    for (int j = 0; j < 8; ++j) {
        float2 tv = *(const float2*)(Tb + 8 * j);
        O[j][0] += cM * tv.x;  O[j][1] += cM * tv.y;
        O[j][2] += cM * tv.x;  O[j][3] += cM * tv.y;
    }

    int r0 = q0 + (w << 4) + (l >> 2);
    int r1 = r0 + 8;
    float* o0 = Og + (size_t)bh * SEQ * DIM + (size_t)r0 * DIM + 2 * (l & 3);
    float* o1 = Og + (size_t)bh * SEQ * DIM + (size_t)r1 * DIM + 2 * (l & 3);
#pragma unroll
    for (int j = 0; j < 8; ++j) {
        *(float2*)(o0 + 8 * j) = make_float2(O[j][0] * invA, O[j][1] * invA);
        *(float2*)(o1 + 8 * j) = make_float2(O[j][2] * invB, O[j][3] * invB);
    }
}

extern "C" void kernel_launch(void* const* d_in, const int* in_sizes, int n_in,
                              void* d_out, int out_size) {
    const float* Q  = (const float*)d_in[0];
    const float* K  = (const float*)d_in[1];
    const float* V  = (const float*)d_in[2];
    const void*  VL = (const void*)d_in[3];
    float*       O  = (float*)d_out;

    cudaFuncSetAttribute(attn_hmma_kernel,
                         cudaFuncAttributeMaxDynamicSharedMemorySize, SMEM_SZ);

    tail_colsum_kernel<<<128, 256>>>(V, VL);

    dim3 grid(SEQ / BQ, 128);   // (16, 128) = 2048 CTAs
    attn_hmma_kernel<<<grid, NTH, SMEM_SZ>>>(Q, K, V, VL, O);
}

// round 15
// speedup vs baseline: 12.0594x; 1.8060x over previous
#include <cuda_runtime.h>
#include <cuda_fp16.h>
#include <cstdint>

// Problem constants: B=8, H=16, S=1024, D=64
#define SEQ  1024
#define DIM  64
#define BQ   64           // q rows per CTA
#define BK   32           // keys per tile
#define NTH  128          // 4 warps; warp w owns rows 16w..16w+15

// smem byte offsets (tiles are [rows][64] fp16, 128B rows, XOR-swizzled)
#define SM_QH  0          // 64 x 128B = 8192
#define SM_KH  8192       // 32 x 128B = 4096
#define SM_VH  12288      // 32 x 128B = 4096
#define SMEM_SZ 16384

// per-(bh) ALIGNED tail column sums: T[bh][d] = sum_{k >= BK*ceil(vl/BK)} V[bh][k][d]
// (keys in [vl, BK*ceil(vl/BK)) are handled IN-LOOP via the 1e-6 masked fill)
__device__ float g_T[128 * DIM];

__device__ __forceinline__ uint32_t smem_u32(const void* p) {
    uint32_t a;
    asm("{ .reg .u64 t; cvta.to.shared.u64 t, %1; cvt.u32.u64 %0, t; }" : "=r"(a) : "l"(p));
    return a;
}
__device__ __forceinline__ void ldsm4(uint32_t* f, uint32_t a) {
    asm volatile("ldmatrix.sync.aligned.m8n8.x4.shared.b16 {%0,%1,%2,%3}, [%4];"
                 : "=r"(f[0]), "=r"(f[1]), "=r"(f[2]), "=r"(f[3]) : "r"(a));
}
__device__ __forceinline__ void ldsm4t(uint32_t* f, uint32_t a) {
    asm volatile("ldmatrix.sync.aligned.m8n8.x4.trans.shared.b16 {%0,%1,%2,%3}, [%4];"
                 : "=r"(f[0]), "=r"(f[1]), "=r"(f[2]), "=r"(f[3]) : "r"(a));
}
__device__ __forceinline__ void mma16816(float* c, const uint32_t* a, const uint32_t* b) {
    asm volatile("mma.sync.aligned.m16n8k16.row.col.f32.f16.f16.f32 "
                 "{%0,%1,%2,%3},{%4,%5,%6,%7},{%8,%9},{%0,%1,%2,%3};"
                 : "+f"(c[0]), "+f"(c[1]), "+f"(c[2]), "+f"(c[3])
                 : "r"(a[0]), "r"(a[1]), "r"(a[2]), "r"(a[3]), "r"(b[0]), "r"(b[1]));
}
// pack two floats into one fp16x2 word
__device__ __forceinline__ uint32_t pack2(float a, float b) {
    __half2 h = __floats2half2_rn(a, b);
    return *(uint32_t*)&h;
}
// valid_lens dtype probe (reference says int64; JAX w/o x64 emits int32)
__device__ __forceinline__ int load_vl(const void* vlp, int b) {
    const int* p32 = (const int*)vlp;
    bool is64 = (p32[1] == 0) && (p32[3] == 0) && (p32[5] == 0) && (p32[7] == 0);
    return is64 ? (int)((const long long*)vlp)[b] : p32[b];
}

// ---- prepass: ALIGNED tail column sums over keys beyond the last processed tile ----
__global__ void tail_colsum_kernel(const float* __restrict__ Vg,
                                   const void* __restrict__ VL)
{
    __shared__ float red[256];
    const int bh = blockIdx.x;              // 128 blocks
    const int vl = load_vl(VL, bh >> 4);
    const int start = ((vl + BK - 1) / BK) * BK;   // BK*ceil(vl/BK)
    const int t  = threadIdx.x;             // 256 threads
    const int d  = t & 63, rg = t >> 6;     // 4 row-groups x 64 dims
    const float* Vb = Vg + (size_t)bh * SEQ * DIM;
    float acc = 0.0f;
    for (int r = start + rg; r < SEQ; r += 4) acc += Vb[r * DIM + d];
    red[t] = acc;
    __syncthreads();
    if (rg == 0)
        g_T[bh * DIM + d] = red[d] + red[64 + d] + red[128 + d] + red[192 + d];
}

__global__ __launch_bounds__(NTH, 3)
void attn_hmma_kernel(const float* __restrict__ Qg,
                      const float* __restrict__ Kg,
                      const float* __restrict__ Vg,
                      const void* __restrict__ VL,
                      float* __restrict__ Og)
{
    extern __shared__ __align__(1024) char smem[];
    const uint32_t sb = smem_u32(smem);
    const int tid = threadIdx.x;
    const int w   = tid >> 5;                // 0..3
    const int l   = tid & 31;
    const int bh  = blockIdx.y;
    const int q0  = blockIdx.x * BQ;
    const int vl  = load_vl(VL, bh >> 4);
    const int nt  = (vl + BK - 1) / BK;      // 32-key tiles with any valid key

    const float4* Q4 = (const float4*)(Qg + (size_t)bh * SEQ * DIM + (size_t)q0 * DIM);
    const float4* K4 = (const float4*)(Kg + (size_t)bh * SEQ * DIM);
    const float4* V4 = (const float4*)(Vg + (size_t)bh * SEQ * DIM);

    // ---- Q: load, scale 0.125, cvt fp16 -> smem (once) ----
#pragma unroll
    for (int i = 0; i < 8; ++i) {                 // 1024 float4 / 128 thr
        int idx = i * NTH + tid;
        int row = idx >> 4, grp = idx & 15;
        float4 x = Q4[idx];
        uint32_t h0 = pack2(x.x * 0.125f, x.y * 0.125f);
        uint32_t h1 = pack2(x.z * 0.125f, x.w * 0.125f);
        uint32_t off = row * 128 + ((grp * 8) ^ ((row & 7) << 4));
        *(uint2*)(smem + SM_QH + off) = make_uint2(h0, h1);
    }

    // prefetch K/V tile 0 into registers (32x64 f32 = 512 f4 each / 128 thr = 4)
    float4 kp[4], vp[4];
#pragma unroll
    for (int i = 0; i < 4; ++i) { kp[i] = K4[i * NTH + tid]; vp[i] = V4[i * NTH + tid]; }

    float O[8][4];
#pragma unroll
    for (int j = 0; j < 8; ++j)
#pragma unroll
        for (int e = 0; e < 4; ++e) O[j][e] = 0.0f;
    float lsA = 0.0f, lsB = 0.0f;

    // per-lane ldmatrix addressing constants
    const int arow = (w << 4) + ((l >> 3) & 1) * 8 + (l & 7);  // Q A-frag row
    const uint32_t aX   = (uint32_t)((arow & 7) << 4);
    const uint32_t aRB  = (uint32_t)(arow * 128);
    const uint32_t aKE  = (uint32_t)((l >> 4) << 4);           // +16B for k8..15 groups
    const uint32_t lx   = (uint32_t)((l & 7) << 4);            // swizzle xor for K/V rows

    __syncthreads();   // Q smem visible

    // ---- Q A-fragments, hoisted: tile-invariant ----
    uint32_t qh[4][4];
#pragma unroll
    for (int kf = 0; kf < 4; ++kf) {
        uint32_t ao = aRB + (((uint32_t)(kf * 32) + aKE) ^ aX);
        ldsm4(qh[kf], sb + SM_QH + ao);
    }

#pragma unroll 1
    for (int kt = 0; kt < nt; ++kt) {
        const int k0 = kt * BK;

        // ---- store prefetched K/V tile: cvt fp16 -> smem ----
#pragma unroll
        for (int i = 0; i < 4; ++i) {
            int idx = i * NTH + tid;
            int row = idx >> 4, grp = idx & 15;
            uint32_t off = row * 128 + ((grp * 8) ^ ((row & 7) << 4));
            *(uint2*)(smem + SM_KH + off) =
                make_uint2(pack2(kp[i].x, kp[i].y), pack2(kp[i].z, kp[i].w));
            *(uint2*)(smem + SM_VH + off) =
                make_uint2(pack2(vp[i].x, vp[i].y), pack2(vp[i].z, vp[i].w));
        }
        __syncthreads();

        // prefetch next tile (clamped; in flight during MMAs)
        {
            int nkt = (kt < nt - 1) ? kt + 1 : kt;
#pragma unroll
            for (int i = 0; i < 4; ++i) {
                kp[i] = K4[nkt * 512 + i * NTH + tid];
                vp[i] = V4[nkt * 512 + i * NTH + tid];
            }
        }

        // ---- GEMM1: S = q k^T (single-pass fp16, paired accumulators) ----
        float S[4][4];
#pragma unroll
        for (int jp = 0; jp < 2; ++jp) {
            const int j0 = 2 * jp, j1 = 2 * jp + 1;
#pragma unroll
            for (int e = 0; e < 4; ++e) { S[j0][e] = 0.0f; S[j1][e] = 0.0f; }
            uint32_t b0[4][2], b1[4][2];
            uint32_t rb0 = (uint32_t)((8 * j0 + (l & 7)) * 128);
            uint32_t rb1 = (uint32_t)((8 * j1 + (l & 7)) * 128);
#pragma unroll
            for (int c = 0; c < 4; c += 2) {
                uint32_t ko = ((uint32_t)(c * 32) + ((uint32_t)(l >> 3) << 4)) ^ lx;
                ldsm4(&b0[c][0], sb + SM_KH + rb0 + ko);
                ldsm4(&b1[c][0], sb + SM_KH + rb1 + ko);
            }
#pragma unroll
            for (int kf = 0; kf < 4; ++kf) {
                mma16816(S[j0], qh[kf], b0[kf]);
                mma16816(S[j1], qh[kf], b1[kf]);
            }
        }

        // ---- mask (1e-6 fill) + exp + lsum + pack P into A-frag layout ----
        uint32_t ph[2][4];
#pragma unroll
        for (int j = 0; j < 4; ++j) {
            int cA = k0 + 8 * j + 2 * (l & 3);
            float c0 = (cA     < vl) ? S[j][0] : 1e-6f;
            float c1 = (cA + 1 < vl) ? S[j][1] : 1e-6f;
            float c2 = (cA     < vl) ? S[j][2] : 1e-6f;
            float c3 = (cA + 1 < vl) ? S[j][3] : 1e-6f;
            float p0 = __expf(c0), p1 = __expf(c1);
            float p2 = __expf(c2), p3 = __expf(c3);
            lsA += p0 + p1;
            lsB += p2 + p3;
            int kf = j >> 1, h = (j & 1) * 2;
            ph[kf][h]     = pack2(p0, p1);
            ph[kf][h + 1] = pack2(p2, p3);
        }

        // ---- GEMM2: O += P V (single-pass fp16, paired accumulators) ----
        {
            const int vrow = ((l >> 4) << 4) + (((l >> 3) & 1) << 3) + (l & 7);
            const uint32_t vrb = (uint32_t)(vrow * 128);
#pragma unroll
            for (int jp = 0; jp < 4; ++jp) {
                const int j0 = 2 * jp, j1 = 2 * jp + 1;
                uint32_t b0[2][2], b1[2][2];
                ldsm4t(&b0[0][0], sb + SM_VH + vrb + (((uint32_t)(16 * j0)) ^ lx));
                ldsm4t(&b1[0][0], sb + SM_VH + vrb + (((uint32_t)(16 * j1)) ^ lx));
#pragma unroll
                for (int kf = 0; kf < 2; ++kf) {
                    mma16816(O[j0], ph[kf], b0[kf]);
                    mma16816(O[j1], ph[kf], b1[kf]);
                }
            }
        }
        __syncthreads();
    }

    // ---- epilogue ----
    // keys beyond nt*BK (never touched in-loop): each contributes p = exp(1e-6)
    const float cM    = __expf(1e-6f);
    const float tailn = (float)(SEQ - nt * BK);

    lsA += __shfl_xor_sync(0xffffffffu, lsA, 1);
    lsA += __shfl_xor_sync(0xffffffffu, lsA, 2);
    lsB += __shfl_xor_sync(0xffffffffu, lsB, 1);
    lsB += __shfl_xor_sync(0xffffffffu, lsB, 2);
    lsA += cM * tailn;
    lsB += cM * tailn;
    float invA = 1.0f / lsA, invB = 1.0f / lsB;

    // O += cM * T[bh][col]  (aligned-tail value mass, exact f32)
    const float* Tb = g_T + bh * DIM + 2 * (l & 3);
#pragma unroll
    for (int j = 0; j < 8; ++j) {
        float2 tv = *(const float2*)(Tb + 8 * j);
        O[j][0] += cM * tv.x;  O[j][1] += cM * tv.y;
        O[j][2] += cM * tv.x;  O[j][3] += cM * tv.y;
    }

    int r0 = q0 + (w << 4) + (l >> 2);
    int r1 = r0 + 8;
    float* o0 = Og + (size_t)bh * SEQ * DIM + (size_t)r0 * DIM + 2 * (l & 3);
    float* o1 = Og + (size_t)bh * SEQ * DIM + (size_t)r1 * DIM + 2 * (l & 3);
#pragma unroll
    for (int j = 0; j < 8; ++j) {
        *(float2*)(o0 + 8 * j) = make_float2(O[j][0] * invA, O[j][1] * invA);
        *(float2*)(o1 + 8 * j) = make_float2(O[j][2] * invB, O[j][3] * invB);
    }
}

extern "C" void kernel_launch(void* const* d_in, const int* in_sizes, int n_in,
                              void* d_out, int out_size) {
    const float* Q  = (const float*)d_in[0];
    const float* K  = (const float*)d_in[1];
    const float* V  = (const float*)d_in[2];
    const void*  VL = (const void*)d_in[3];
    float*       O  = (float*)d_out;

    cudaFuncSetAttribute(attn_hmma_kernel,
                         cudaFuncAttributeMaxDynamicSharedMemorySize, SMEM_SZ);

    tail_colsum_kernel<<<128, 256>>>(V, VL);

    dim3 grid(SEQ / BQ, 128);   // (16, 128) = 2048 CTAs
    attn_hmma_kernel<<<grid, NTH, SMEM_SZ>>>(Q, K, V, VL, O);
}